// round 11
// baseline (speedup 1.0000x reference)
#include <cuda_runtime.h>
#include <cstdint>

// Problem constants
#define B_  2
#define L_  64
#define D_  1024
#define H_  512
#define S_  50000
#define V_  40000
#define K_  32
#define M_  128            // B*L rows
#define SLM_SCALE 0.1f
#define BN_EPS 1e-5f

// ---------------- scratch (device globals; no allocation allowed) ----------
__device__ float g_scale[L_];
__device__ float g_shift[L_];
__device__ float g_h[M_ * H_];                    // 256 KB, tf32-rounded
__device__ uint32_t g_vT2[(size_t)V_ * 64];       // 10.24 MB: pair(row j, row j+64)

// ---------------- helpers ---------------------------------------------------
__device__ __forceinline__ uint32_t smem_u32(const void* p) {
    uint32_t a;
    asm("{ .reg .u64 t; cvta.to.shared.u64 t, %1; cvt.u32.u64 %0, t; }"
        : "=r"(a) : "l"(p));
    return a;
}
__device__ __forceinline__ float rna_tf32(float x) {
    uint32_t r;
    asm("cvt.rna.tf32.f32 %0, %1;" : "=r"(r) : "f"(x));
    return __uint_as_float(r);
}
__device__ __forceinline__ uint32_t rna_tf32_u(float x) {
    uint32_t r;
    asm("cvt.rna.tf32.f32 %0, %1;" : "=r"(r) : "f"(x));
    return r;
}
__device__ __forceinline__ uint32_t pack_bf16(float hi, float lo) {
    uint32_t r;
    asm("cvt.rn.bf16x2.f32 %0, %1, %2;" : "=r"(r) : "f"(hi), "f"(lo));
    return r;
}
__device__ __forceinline__ float bf_lo(uint32_t u) { return __uint_as_float(u << 16); }
__device__ __forceinline__ float bf_hi(uint32_t u) { return __uint_as_float(u & 0xffff0000u); }

__device__ __forceinline__ void cp16(uint32_t dst, const void* src) {
    asm volatile("cp.async.cg.shared.global [%0], [%1], 16;"
                 :: "r"(dst), "l"(src));
}
__device__ __forceinline__ void cp16z(uint32_t dst, const void* src, int sz) {
    asm volatile("cp.async.cg.shared.global [%0], [%1], 16, %2;"
                 :: "r"(dst), "l"(src), "r"(sz));
}
__device__ __forceinline__ void mma_tf32(float& c0, float& c1, float& c2, float& c3,
                                         uint32_t a0, uint32_t a1, uint32_t a2, uint32_t a3,
                                         uint32_t b0, uint32_t b1) {
    asm volatile("mma.sync.aligned.m16n8k8.row.col.f32.tf32.tf32.f32 "
                 "{%0,%1,%2,%3}, {%4,%5,%6,%7}, {%8,%9}, {%0,%1,%2,%3};"
                 : "+f"(c0), "+f"(c1), "+f"(c2), "+f"(c3)
                 : "r"(a0), "r"(a1), "r"(a2), "r"(a3), "r"(b0), "r"(b1));
}

// ---------------- kernel 1: BN stats per channel l --------------------------
__global__ void bn_stats_kernel(const float* __restrict__ x,
                                const float* __restrict__ gamma,
                                const float* __restrict__ beta) {
    int l = blockIdx.x;
    int tid = threadIdx.x;
    const float* r0 = x + (size_t)l * D_;
    const float* r1 = x + (size_t)(L_ + l) * D_;
    float s = 0.f, ss = 0.f;
    for (int d = tid; d < D_; d += blockDim.x) {
        float a = r0[d], b = r1[d];
        s  += a + b;
        ss += a * a + b * b;
    }
    __shared__ float sh_s[8], sh_ss[8];
    #pragma unroll
    for (int o = 16; o; o >>= 1) {
        s  += __shfl_down_sync(0xffffffffu, s,  o);
        ss += __shfl_down_sync(0xffffffffu, ss, o);
    }
    int w = tid >> 5;
    if ((tid & 31) == 0) { sh_s[w] = s; sh_ss[w] = ss; }
    __syncthreads();
    if (tid == 0) {
        float S = 0.f, SS = 0.f;
        #pragma unroll
        for (int i = 0; i < 8; i++) { S += sh_s[i]; SS += sh_ss[i]; }
        float inv_n = 1.0f / (2.0f * D_);
        float mean = S * inv_n;
        float var  = SS * inv_n - mean * mean;
        float sc = gamma[l] * rsqrtf(var + BN_EPS);
        g_scale[l] = sc;
        g_shift[l] = beta[l] - mean * sc;
    }
}

// ---------------- kernel 2: h = relu(xn @ W1 + b1), tf32-rounded ------------
// grid 32: block handles l0, l0+32, both batches -> 4 rows per thread.
// W1 traffic: 32 blocks x 2MB = 64MB (vs 268MB at one block per row).
__global__ void __launch_bounds__(512)
h_kernel(const float* __restrict__ x,
         const float* __restrict__ W1,
         const float* __restrict__ b1) {
    int l0 = blockIdx.x;            // 0..31
    int j  = threadIdx.x;           // 0..511
    __shared__ float xs[4][D_];     // rows: l0, l0+32, 64+l0, 96+l0
    float sc0 = g_scale[l0],      sh0 = g_shift[l0];
    float sc1 = g_scale[l0 + 32], sh1 = g_shift[l0 + 32];
    const int rows[4] = {l0, l0 + 32, 64 + l0, 96 + l0};
    const float scs[4] = {sc0, sc1, sc0, sc1};
    const float shs[4] = {sh0, sh1, sh0, sh1};
    #pragma unroll
    for (int r = 0; r < 4; r++) {
        const float* xr = x + (size_t)rows[r] * D_;
        for (int d = j; d < D_; d += 512)
            xs[r][d] = xr[d] * scs[r] + shs[r];
    }
    __syncthreads();
    float a0 = b1[j], a1 = a0, a2 = a0, a3 = a0;
    #pragma unroll 8
    for (int d = 0; d < D_; d++) {
        float w = W1[(size_t)d * H_ + j];
        a0 += xs[0][d] * w;
        a1 += xs[1][d] * w;
        a2 += xs[2][d] * w;
        a3 += xs[3][d] * w;
    }
    g_h[(size_t)rows[0] * H_ + j] = rna_tf32(fmaxf(a0, 0.f));
    g_h[(size_t)rows[1] * H_ + j] = rna_tf32(fmaxf(a1, 0.f));
    g_h[(size_t)rows[2] * H_ + j] = rna_tf32(fmaxf(a2, 0.f));
    g_h[(size_t)rows[3] * H_ + j] = rna_tf32(fmaxf(a3, 0.f));
}

// ---------------- GEMM tiling constants -------------------------------------
#define NBLK 128
#define KC   32
#define SA   36                 // A smem stride (floats)
#define SBr  136                // B smem stride (floats)
#define A_SZ (128 * SA)         // 4608 floats
#define B_SZ (KC * SBr)         // 4352 floats
#define PAIR (A_SZ + B_SZ)      // 8960 floats
#define PIPE_F (2 * PAIR)       // 17920 floats
#define SC   132                // transpose stride (floats, gemm_v)
#define CYP  133                // Cy stride (odd -> conflict-free)
#define CGP  129                // Cg stride (odd -> conflict-free)

// ---------------- GEMM mainloop (shared) ------------------------------------
struct GemmCtx {
    int tid, mw, nw, g, tig, n0;
};

__device__ __forceinline__ void gemm_barrier(int use_named) {
    if (use_named)
        asm volatile("bar.sync 1, 256;" ::: "memory");
    else
        __syncthreads();
}

template <int NAMED>
__device__ __forceinline__ void gemm_mainloop(
        float* smem, uint32_t sbase, const float* __restrict__ Wmat, int N,
        const GemmCtx& t, float c[4][4][4]) {
    auto stage = [&](int it, int buf) {
        int k0 = it * KC;
        uint32_t a_s = sbase + (uint32_t)(buf * PAIR) * 4u;
        uint32_t b_s = a_s + (uint32_t)A_SZ * 4u;
        #pragma unroll
        for (int i = 0; i < 4; i++) {
            int q = t.tid + i * 256;             // 0..1023
            int row = q >> 3, c4 = q & 7;
            cp16(a_s + (uint32_t)(row * SA + c4 * 4) * 4u,
                 &g_h[(size_t)row * H_ + k0 + c4 * 4]);
        }
        #pragma unroll
        for (int i = 0; i < 4; i++) {
            int q = t.tid + i * 256;             // 0..1023
            int kr = q >> 5, c4 = q & 31;
            int col = t.n0 + c4 * 4;
            cp16z(b_s + (uint32_t)(kr * SBr + c4 * 4) * 4u,
                  Wmat + (size_t)(k0 + kr) * N + col,
                  (col < N) ? 16 : 0);
        }
    };

    stage(0, 0);
    asm volatile("cp.async.commit_group;" ::: "memory");

    const int ITER = H_ / KC;                    // 16
    for (int it = 0; it < ITER; ++it) {
        int buf = it & 1;
        if (it + 1 < ITER) {
            stage(it + 1, buf ^ 1);
            asm volatile("cp.async.commit_group;" ::: "memory");
            asm volatile("cp.async.wait_group 1;" ::: "memory");
        } else {
            asm volatile("cp.async.wait_group 0;" ::: "memory");
        }
        gemm_barrier(NAMED);

        const float* Af = smem + buf * PAIR;
        const float* Bf = Af + A_SZ;

        #pragma unroll
        for (int ks = 0; ks < 4; ks++) {
            uint32_t a[4][4], b[4][2];
            int kc = ks * 8 + t.tig;
            #pragma unroll
            for (int mf = 0; mf < 4; mf++) {
                int r = t.mw * 64 + mf * 16 + t.g;
                a[mf][0] = __float_as_uint(Af[r * SA + kc]);
                a[mf][1] = __float_as_uint(Af[(r + 8) * SA + kc]);
                a[mf][2] = __float_as_uint(Af[r * SA + kc + 4]);
                a[mf][3] = __float_as_uint(Af[(r + 8) * SA + kc + 4]);
            }
            #pragma unroll
            for (int nf = 0; nf < 4; nf++) {
                int ncol = t.nw * 32 + nf * 8 + t.g;
                b[nf][0] = rna_tf32_u(Bf[kc * SBr + ncol]);
                b[nf][1] = rna_tf32_u(Bf[(kc + 4) * SBr + ncol]);
            }
            #pragma unroll
            for (int mf = 0; mf < 4; mf++)
                #pragma unroll
                for (int nf = 0; nf < 4; nf++)
                    mma_tf32(c[mf][nf][0], c[mf][nf][1], c[mf][nf][2], c[mf][nf][3],
                             a[mf][0], a[mf][1], a[mf][2], a[mf][3],
                             b[nf][0], b[nf][1]);
        }
        gemm_barrier(NAMED);
    }
}

// ---------------- kernel 3: v-GEMM -> g_vT2 (bf16 pairs (j, j+64)) ----------
#define GEMMV_SMEM (PIPE_F * 4)   // 71680 B

__global__ void __launch_bounds__(256, 2)
gemm_v_kernel(const float* __restrict__ Wmat,
              const float* __restrict__ bias, int N) {
    extern __shared__ float smem[];
    const uint32_t sbase = smem_u32(smem);
    int tid = threadIdx.x, wid = tid >> 5, lane = tid & 31;
    GemmCtx t;
    t.tid = tid;
    t.mw = wid >> 2; t.nw = wid & 3;
    t.g = lane >> 2; t.tig = lane & 3;
    t.n0 = blockIdx.x * NBLK;

    float c[4][4][4];
    #pragma unroll
    for (int mf = 0; mf < 4; mf++)
        #pragma unroll
        for (int nf = 0; nf < 4; nf++)
            #pragma unroll
            for (int i = 0; i < 4; i++) c[mf][nf][i] = 0.f;

    gemm_mainloop<0>(smem, sbase, Wmat, N, t, c);

    // transpose through smem, pack (row j, row j+64) into bf16x2
    float* Cs = smem;
    #pragma unroll
    for (int mf = 0; mf < 4; mf++) {
        int m = t.mw * 64 + mf * 16 + t.g;
        #pragma unroll
        for (int nf = 0; nf < 4; nf++) {
            int ncol = t.nw * 32 + nf * 8 + 2 * t.tig;
            Cs[ncol * SC + m]           = c[mf][nf][0];
            Cs[(ncol + 1) * SC + m]     = c[mf][nf][1];
            Cs[ncol * SC + m + 8]       = c[mf][nf][2];
            Cs[(ncol + 1) * SC + m + 8] = c[mf][nf][3];
        }
    }
    __syncthreads();
    #pragma unroll
    for (int i = 0; i < 16; i++) {
        int q = tid + i * 256;            // 0..4095
        int jp = (q & 31) * 2;            // pair row 0..62 (even)
        int col = t.n0 + (q >> 5);
        if (col < N) {
            float bv = bias[col];
            float2 lo2 = *reinterpret_cast<const float2*>(&Cs[(q >> 5) * SC + jp]);
            float2 hi2 = *reinterpret_cast<const float2*>(&Cs[(q >> 5) * SC + jp + 64]);
            uint2 p;
            p.x = pack_bf16(hi2.x + bv, lo2.x + bv);   // rows (jp, jp+64)
            p.y = pack_bf16(hi2.y + bv, lo2.y + bv);   // rows (jp+1, jp+65)
            *reinterpret_cast<uint2*>(&g_vT2[(size_t)col * 64 + jp]) = p;
        }
    }
}

// ---------------- kernel 4: warp-specialized y-GEMM + gather ----------------
// 512 threads: warps 0-7 GEMM (bar.sync 1,256), warps 8-15 gather (bar 2,256).
// smem (floats): [0, PIPE_F) pipeline / Cy(133); [SIDX_F,+4096) sidx;
//                [SWT_F,+4096) swt; [CG_F, +128*129) Cg
#define SIDX_F PIPE_F
#define SWT_F  (PIPE_F + 4096)
#define CG_F   (SWT_F + 4096)
#define FUSED_F (CG_F + 128 * CGP)             // 42624 floats
#define FUSED_SMEM (FUSED_F * 4)               // 170496 B

__global__ void __launch_bounds__(512, 1)
gemm_y_gather_kernel(const float* __restrict__ Wmat,
                     const float* __restrict__ bias,
                     const int* __restrict__ sl_idx,
                     const float* __restrict__ sl_w,
                     float* __restrict__ outp) {
    extern __shared__ float smem[];
    const uint32_t sbase = smem_u32(smem);
    int tid = threadIdx.x;
    int n0 = blockIdx.x * NBLK;
    float* Cy = smem;                 // stride CYP, valid after mainloop
    float* Cg = smem + CG_F;          // stride CGP

    if (tid < 256) {
        // ================= GEMM half =================
        int wid = tid >> 5, lane = tid & 31;
        GemmCtx t;
        t.tid = tid;
        t.mw = wid >> 2; t.nw = wid & 3;
        t.g = lane >> 2; t.tig = lane & 3;
        t.n0 = n0;

        float c[4][4][4];
        #pragma unroll
        for (int mf = 0; mf < 4; mf++)
            #pragma unroll
            for (int nf = 0; nf < 4; nf++)
                #pragma unroll
                for (int i = 0; i < 4; i++) c[mf][nf][i] = 0.f;

        gemm_mainloop<1>(smem, sbase, Wmat, S_, t, c);

        // scatter frags to Cy (pipeline region is free after last barrier)
        #pragma unroll
        for (int mf = 0; mf < 4; mf++) {
            int row = t.mw * 64 + mf * 16 + t.g;
            #pragma unroll
            for (int nf = 0; nf < 4; nf++) {
                int cl = t.nw * 32 + nf * 8 + 2 * t.tig;
                Cy[row * CYP + cl]           = c[mf][nf][0];
                Cy[row * CYP + cl + 1]       = c[mf][nf][1];
                Cy[(row + 8) * CYP + cl]     = c[mf][nf][2];
                Cy[(row + 8) * CYP + cl + 1] = c[mf][nf][3];
            }
        }
    } else {
        // ================= gather half =================
        int gtid = tid - 256;         // 0..255
        int*   sidx = reinterpret_cast<int*>(smem + SIDX_F);
        float* swt  = smem + SWT_F;
        // load indices + weights for this block's 128 s-cols
        for (int e = gtid; e < NBLK * K_; e += 256) {
            int s = e >> 5;           // K_=32
            bool ok = (n0 + s) < S_;
            sidx[e] = ok ? sl_idx[(size_t)(n0 + s) * K_ + (e & 31)] : 0;
            swt[e]  = ok ? sl_w[(size_t)(n0 + s) * K_ + (e & 31)]   : 0.f;
        }
        asm volatile("bar.sync 2, 256;" ::: "memory");

        int r2 = gtid & 63;           // rows r2, r2+64
        int quarter = gtid >> 6;      // s range [32q, 32q+32)
        const uint32_t* vp = g_vT2 + r2;

        for (int si = 0; si < 32; si++) {
            int s = quarter * 32 + si;
            const int*   ip = sidx + s * K_;
            const float* wp = swt  + s * K_;
            float a0 = 0.f, a1 = 0.f, a2 = 0.f, a3 = 0.f;
            float b0 = 0.f, b1 = 0.f, b2 = 0.f, b3 = 0.f;
            #pragma unroll
            for (int k = 0; k < K_; k += 8) {
                uint32_t u0 = vp[(size_t)ip[k + 0] * 64];
                uint32_t u1 = vp[(size_t)ip[k + 1] * 64];
                uint32_t u2 = vp[(size_t)ip[k + 2] * 64];
                uint32_t u3 = vp[(size_t)ip[k + 3] * 64];
                uint32_t u4 = vp[(size_t)ip[k + 4] * 64];
                uint32_t u5 = vp[(size_t)ip[k + 5] * 64];
                uint32_t u6 = vp[(size_t)ip[k + 6] * 64];
                uint32_t u7 = vp[(size_t)ip[k + 7] * 64];
                float w0 = wp[k + 0], w1 = wp[k + 1], w2 = wp[k + 2], w3 = wp[k + 3];
                float w4 = wp[k + 4], w5 = wp[k + 5], w6 = wp[k + 6], w7 = wp[k + 7];
                a0 += w0 * bf_lo(u0); b0 += w0 * bf_hi(u0);
                a1 += w1 * bf_lo(u1); b1 += w1 * bf_hi(u1);
                a2 += w2 * bf_lo(u2); b2 += w2 * bf_hi(u2);
                a3 += w3 * bf_lo(u3); b3 += w3 * bf_hi(u3);
                a0 += w4 * bf_lo(u4); b0 += w4 * bf_hi(u4);
                a1 += w5 * bf_lo(u5); b1 += w5 * bf_hi(u5);
                a2 += w6 * bf_lo(u6); b2 += w6 * bf_hi(u6);
                a3 += w7 * bf_lo(u7); b3 += w7 * bf_hi(u7);
            }
            Cg[r2 * CGP + s]        = (a0 + a1) + (a2 + a3);
            Cg[(r2 + 64) * CGP + s] = (b0 + b1) + (b2 + b3);
        }
    }
    __syncthreads();

    // ---- combined epilogue: out = Cy + bias + SLM_SCALE * Cg ----
    #pragma unroll
    for (int i = 0; i < 8; i++) {
        int q = tid + i * 512;            // 0..4095
        int row = q >> 5, c4 = (q & 31) * 4;
        int col = n0 + c4;
        if (col < S_) {                   // S % 4 == 0
            float4 bv = *reinterpret_cast<const float4*>(bias + col);
            const float* cy = &Cy[row * CYP + c4];
            const float* cg = &Cg[row * CGP + c4];
            float4 o;
            o.x = cy[0] + bv.x + SLM_SCALE * cg[0];
            o.y = cy[1] + bv.y + SLM_SCALE * cg[1];
            o.z = cy[2] + bv.z + SLM_SCALE * cg[2];
            o.w = cy[3] + bv.w + SLM_SCALE * cg[3];
            *reinterpret_cast<float4*>(&outp[(size_t)row * S_ + col]) = o;
        }
    }
}

// ---------------- launch ----------------------------------------------------
extern "C" void kernel_launch(void* const* d_in, const int* in_sizes, int n_in,
                              void* d_out, int out_size) {
    const float* x     = (const float*)d_in[0];
    const float* gamma = (const float*)d_in[1];
    const float* beta  = (const float*)d_in[2];
    const float* W1    = (const float*)d_in[3];
    const float* b1    = (const float*)d_in[4];
    const float* W2    = (const float*)d_in[5];
    const float* b2    = (const float*)d_in[6];
    const float* Wslm  = (const float*)d_in[7];
    const float* bslm  = (const float*)d_in[8];
    const float* slw   = (const float*)d_in[9];
    const int*   sli   = (const int*)d_in[10];
    float* out = (float*)d_out;

    cudaFuncSetAttribute(gemm_v_kernel,
                         cudaFuncAttributeMaxDynamicSharedMemorySize, GEMMV_SMEM);
    cudaFuncSetAttribute(gemm_y_gather_kernel,
                         cudaFuncAttributeMaxDynamicSharedMemorySize, FUSED_SMEM);

    bn_stats_kernel<<<L_, 256>>>(x, gamma, beta);
    h_kernel<<<32, 512>>>(x, W1, b1);
    gemm_v_kernel<<<(V_ + NBLK - 1) / NBLK, 256, GEMMV_SMEM>>>(Wslm, bslm, V_);
    gemm_y_gather_kernel<<<(S_ + NBLK - 1) / NBLK, 512, FUSED_SMEM>>>(
        W2, b2, sli, slw, out);
}

// round 14
// speedup vs baseline: 1.0631x; 1.0631x over previous
#include <cuda_runtime.h>
#include <cstdint>

// Problem constants
#define B_  2
#define L_  64
#define D_  1024
#define H_  512
#define S_  50000
#define V_  40000
#define K_  32
#define M_  128            // B*L rows
#define SLM_SCALE 0.1f
#define BN_EPS 1e-5f

// ---------------- scratch (device globals; no allocation allowed) ----------
__device__ float g_scale[L_];
__device__ float g_shift[L_];
__device__ float g_h[M_ * H_];                    // 256 KB, tf32-rounded
__device__ uint32_t g_vT2[(size_t)V_ * 64];       // 10.24 MB: pair(row j, row j+64)

// ---------------- helpers ---------------------------------------------------
__device__ __forceinline__ uint32_t smem_u32(const void* p) {
    uint32_t a;
    asm("{ .reg .u64 t; cvta.to.shared.u64 t, %1; cvt.u32.u64 %0, t; }"
        : "=r"(a) : "l"(p));
    return a;
}
__device__ __forceinline__ float rna_tf32(float x) {
    uint32_t r;
    asm("cvt.rna.tf32.f32 %0, %1;" : "=r"(r) : "f"(x));
    return __uint_as_float(r);
}
__device__ __forceinline__ uint32_t rna_tf32_u(float x) {
    uint32_t r;
    asm("cvt.rna.tf32.f32 %0, %1;" : "=r"(r) : "f"(x));
    return r;
}
__device__ __forceinline__ uint32_t pack_bf16(float hi, float lo) {
    uint32_t r;
    asm("cvt.rn.bf16x2.f32 %0, %1, %2;" : "=r"(r) : "f"(hi), "f"(lo));
    return r;
}
__device__ __forceinline__ float bf_lo(uint32_t u) { return __uint_as_float(u << 16); }
__device__ __forceinline__ float bf_hi(uint32_t u) { return __uint_as_float(u & 0xffff0000u); }

__device__ __forceinline__ void cp16(uint32_t dst, const void* src) {
    asm volatile("cp.async.cg.shared.global [%0], [%1], 16;"
                 :: "r"(dst), "l"(src));
}
__device__ __forceinline__ void cp16z(uint32_t dst, const void* src, int sz) {
    asm volatile("cp.async.cg.shared.global [%0], [%1], 16, %2;"
                 :: "r"(dst), "l"(src), "r"(sz));
}
__device__ __forceinline__ void mma_tf32(float& c0, float& c1, float& c2, float& c3,
                                         uint32_t a0, uint32_t a1, uint32_t a2, uint32_t a3,
                                         uint32_t b0, uint32_t b1) {
    asm volatile("mma.sync.aligned.m16n8k8.row.col.f32.tf32.tf32.f32 "
                 "{%0,%1,%2,%3}, {%4,%5,%6,%7}, {%8,%9}, {%0,%1,%2,%3};"
                 : "+f"(c0), "+f"(c1), "+f"(c2), "+f"(c3)
                 : "r"(a0), "r"(a1), "r"(a2), "r"(a3), "r"(b0), "r"(b1));
}

// ---------------- kernel 1: BN stats per channel l --------------------------
__global__ void bn_stats_kernel(const float* __restrict__ x,
                                const float* __restrict__ gamma,
                                const float* __restrict__ beta) {
    int l = blockIdx.x;
    int tid = threadIdx.x;
    const float* r0 = x + (size_t)l * D_;
    const float* r1 = x + (size_t)(L_ + l) * D_;
    float s = 0.f, ss = 0.f;
    for (int d = tid; d < D_; d += blockDim.x) {
        float a = r0[d], b = r1[d];
        s  += a + b;
        ss += a * a + b * b;
    }
    __shared__ float sh_s[8], sh_ss[8];
    #pragma unroll
    for (int o = 16; o; o >>= 1) {
        s  += __shfl_down_sync(0xffffffffu, s,  o);
        ss += __shfl_down_sync(0xffffffffu, ss, o);
    }
    int w = tid >> 5;
    if ((tid & 31) == 0) { sh_s[w] = s; sh_ss[w] = ss; }
    __syncthreads();
    if (tid == 0) {
        float S = 0.f, SS = 0.f;
        #pragma unroll
        for (int i = 0; i < 8; i++) { S += sh_s[i]; SS += sh_ss[i]; }
        float inv_n = 1.0f / (2.0f * D_);
        float mean = S * inv_n;
        float var  = SS * inv_n - mean * mean;
        float sc = gamma[l] * rsqrtf(var + BN_EPS);
        g_scale[l] = sc;
        g_shift[l] = beta[l] - mean * sc;
    }
}

// ---------------- kernel 2: h = relu(xn @ W1 + b1), tf32-rounded ------------
// grid (L_, 2): one block per (l, batch) -> 128 blocks  (R10 proven version)
__global__ void h_kernel(const float* __restrict__ x,
                         const float* __restrict__ W1,
                         const float* __restrict__ b1) {
    int l = blockIdx.x, bb = blockIdx.y;
    int j = threadIdx.x;   // 0..511
    __shared__ float xs[D_];
    float sc = g_scale[l], sh = g_shift[l];
    const float* r = x + (size_t)(bb * L_ + l) * D_;
    for (int d = j; d < D_; d += blockDim.x)
        xs[d] = r[d] * sc + sh;
    __syncthreads();
    float a = b1[j];
    #pragma unroll 8
    for (int d = 0; d < D_; d++)
        a += xs[d] * W1[(size_t)d * H_ + j];
    g_h[(size_t)(bb * L_ + l) * H_ + j] = rna_tf32(fmaxf(a, 0.f));
}

// ---------------- GEMM tiling constants -------------------------------------
#define NBLK 128
#define KC   32
#define SA   36                 // A smem stride (floats)
#define SBr  136                // B smem stride (floats)
#define A_SZ (128 * SA)         // 4608 floats
#define B_SZ (KC * SBr)         // 4352 floats
#define PAIR (A_SZ + B_SZ)      // 8960 floats
#define PIPE_F (2 * PAIR)       // 17920 floats
#define SC   132                // transpose stride (floats, gemm_v)
#define CYP  133                // Cy stride (floats, fused; region = pipe)
#define CGS  129                // Cg2 stride (uint32, odd -> conflict-free)

// ---------------- GEMM mainloop (shared) ------------------------------------
struct GemmCtx {
    int tid, mw, nw, g, tig, n0;
};

__device__ __forceinline__ void gemm_mainloop(
        float* smem, uint32_t sbase, const float* __restrict__ Wmat, int N,
        const GemmCtx& t, float c[4][4][4]) {
    auto stage = [&](int it, int buf) {
        int k0 = it * KC;
        uint32_t a_s = sbase + (uint32_t)(buf * PAIR) * 4u;
        uint32_t b_s = a_s + (uint32_t)A_SZ * 4u;
        #pragma unroll
        for (int i = 0; i < 4; i++) {
            int q = t.tid + i * 256;             // 0..1023
            int row = q >> 3, c4 = q & 7;
            cp16(a_s + (uint32_t)(row * SA + c4 * 4) * 4u,
                 &g_h[(size_t)row * H_ + k0 + c4 * 4]);
        }
        #pragma unroll
        for (int i = 0; i < 4; i++) {
            int q = t.tid + i * 256;             // 0..1023
            int kr = q >> 5, c4 = q & 31;
            int col = t.n0 + c4 * 4;
            cp16z(b_s + (uint32_t)(kr * SBr + c4 * 4) * 4u,
                  Wmat + (size_t)(k0 + kr) * N + col,
                  (col < N) ? 16 : 0);
        }
    };

    stage(0, 0);
    asm volatile("cp.async.commit_group;" ::: "memory");

    const int ITER = H_ / KC;                    // 16
    for (int it = 0; it < ITER; ++it) {
        int buf = it & 1;
        if (it + 1 < ITER) {
            stage(it + 1, buf ^ 1);
            asm volatile("cp.async.commit_group;" ::: "memory");
            asm volatile("cp.async.wait_group 1;" ::: "memory");
        } else {
            asm volatile("cp.async.wait_group 0;" ::: "memory");
        }
        __syncthreads();

        const float* Af = smem + buf * PAIR;
        const float* Bf = Af + A_SZ;

        #pragma unroll
        for (int ks = 0; ks < 4; ks++) {
            uint32_t a[4][4], b[4][2];
            int kc = ks * 8 + t.tig;
            #pragma unroll
            for (int mf = 0; mf < 4; mf++) {
                int r = t.mw * 64 + mf * 16 + t.g;
                a[mf][0] = __float_as_uint(Af[r * SA + kc]);
                a[mf][1] = __float_as_uint(Af[(r + 8) * SA + kc]);
                a[mf][2] = __float_as_uint(Af[r * SA + kc + 4]);
                a[mf][3] = __float_as_uint(Af[(r + 8) * SA + kc + 4]);
            }
            #pragma unroll
            for (int nf = 0; nf < 4; nf++) {
                int ncol = t.nw * 32 + nf * 8 + t.g;
                b[nf][0] = rna_tf32_u(Bf[kc * SBr + ncol]);
                b[nf][1] = rna_tf32_u(Bf[(kc + 4) * SBr + ncol]);
            }
            #pragma unroll
            for (int mf = 0; mf < 4; mf++)
                #pragma unroll
                for (int nf = 0; nf < 4; nf++)
                    mma_tf32(c[mf][nf][0], c[mf][nf][1], c[mf][nf][2], c[mf][nf][3],
                             a[mf][0], a[mf][1], a[mf][2], a[mf][3],
                             b[nf][0], b[nf][1]);
        }
        __syncthreads();
    }
}

// ---------------- kernel 3: v-GEMM -> g_vT2 (bf16 pairs (j, j+64)) ----------
#define GEMMV_SMEM (PIPE_F * 4)   // 71680 B

__global__ void __launch_bounds__(256, 2)
gemm_v_kernel(const float* __restrict__ Wmat,
              const float* __restrict__ bias, int N) {
    extern __shared__ float smem[];
    const uint32_t sbase = smem_u32(smem);
    int tid = threadIdx.x, wid = tid >> 5, lane = tid & 31;
    GemmCtx t;
    t.tid = tid;
    t.mw = wid >> 2; t.nw = wid & 3;
    t.g = lane >> 2; t.tig = lane & 3;
    t.n0 = blockIdx.x * NBLK;

    float c[4][4][4];
    #pragma unroll
    for (int mf = 0; mf < 4; mf++)
        #pragma unroll
        for (int nf = 0; nf < 4; nf++)
            #pragma unroll
            for (int i = 0; i < 4; i++) c[mf][nf][i] = 0.f;

    gemm_mainloop(smem, sbase, Wmat, N, t, c);

    // transpose through smem, pack (row j, row j+64) into bf16x2
    float* Cs = smem;
    #pragma unroll
    for (int mf = 0; mf < 4; mf++) {
        int m = t.mw * 64 + mf * 16 + t.g;
        #pragma unroll
        for (int nf = 0; nf < 4; nf++) {
            int ncol = t.nw * 32 + nf * 8 + 2 * t.tig;
            Cs[ncol * SC + m]           = c[mf][nf][0];
            Cs[(ncol + 1) * SC + m]     = c[mf][nf][1];
            Cs[ncol * SC + m + 8]       = c[mf][nf][2];
            Cs[(ncol + 1) * SC + m + 8] = c[mf][nf][3];
        }
    }
    __syncthreads();
    #pragma unroll
    for (int i = 0; i < 16; i++) {
        int q = tid + i * 256;            // 0..4095
        int jp = (q & 31) * 2;            // pair row 0..62 (even)
        int col = t.n0 + (q >> 5);
        if (col < N) {
            float bv = bias[col];
            float2 lo2 = *reinterpret_cast<const float2*>(&Cs[(q >> 5) * SC + jp]);
            float2 hi2 = *reinterpret_cast<const float2*>(&Cs[(q >> 5) * SC + jp + 64]);
            uint2 p;
            p.x = pack_bf16(hi2.x + bv, lo2.x + bv);   // rows (jp, jp+64)
            p.y = pack_bf16(hi2.y + bv, lo2.y + bv);   // rows (jp+1, jp+65)
            *reinterpret_cast<uint2*>(&g_vT2[(size_t)col * 64 + jp]) = p;
        }
    }
}

// ---------------- kernel 4: fused y-GEMM + gather, phase-swapped ------------
// smem (floats): [0, PIPE_F) pipeline (Cy stride CYP after mainloop);
//                [PIPE_F, +64*CGS uint32) Cg2 (bf16x2 row-pair gather sums)
#define CG2_F  PIPE_F
#define FUSED_F (PIPE_F + 64 * CGS)            // 26176 floats
#define FUSED_SMEM (FUSED_F * 4)               // 104704 B

// gather phase: writes Cg2[r2][s] = bf16x2(sum_row_r2+64, sum_row_r2)
__device__ __forceinline__ void do_gather(uint32_t* Cg2,
                                          const int* __restrict__ sl_idx,
                                          const float* __restrict__ sl_w,
                                          int n0, int tid) {
    int r2 = tid & 63;            // row pair (r2, r2+64)
    int quarter = tid >> 6;       // s range [32q, 32q+32)
    const uint32_t* vp = g_vT2 + r2;

    for (int si = 0; si < 32; si++) {
        int s = quarter * 32 + si;
        int scol = n0 + s;
        float a0 = 0.f, a1 = 0.f, a2 = 0.f, a3 = 0.f;
        float b0 = 0.f, b1 = 0.f, b2 = 0.f, b3 = 0.f;
        if (scol < S_) {
            const int*   ip = sl_idx + (size_t)scol * K_;
            const float* wp = sl_w   + (size_t)scol * K_;
            #pragma unroll
            for (int k = 0; k < K_; k += 8) {
                int i0 = __ldg(ip + k + 0), i1 = __ldg(ip + k + 1);
                int i2 = __ldg(ip + k + 2), i3 = __ldg(ip + k + 3);
                int i4 = __ldg(ip + k + 4), i5 = __ldg(ip + k + 5);
                int i6 = __ldg(ip + k + 6), i7 = __ldg(ip + k + 7);
                uint32_t u0 = __ldg(vp + (size_t)i0 * 64);
                uint32_t u1 = __ldg(vp + (size_t)i1 * 64);
                uint32_t u2 = __ldg(vp + (size_t)i2 * 64);
                uint32_t u3 = __ldg(vp + (size_t)i3 * 64);
                uint32_t u4 = __ldg(vp + (size_t)i4 * 64);
                uint32_t u5 = __ldg(vp + (size_t)i5 * 64);
                uint32_t u6 = __ldg(vp + (size_t)i6 * 64);
                uint32_t u7 = __ldg(vp + (size_t)i7 * 64);
                float w0 = __ldg(wp + k + 0), w1 = __ldg(wp + k + 1);
                float w2 = __ldg(wp + k + 2), w3 = __ldg(wp + k + 3);
                float w4 = __ldg(wp + k + 4), w5 = __ldg(wp + k + 5);
                float w6 = __ldg(wp + k + 6), w7 = __ldg(wp + k + 7);
                a0 += w0 * bf_lo(u0); b0 += w0 * bf_hi(u0);
                a1 += w1 * bf_lo(u1); b1 += w1 * bf_hi(u1);
                a2 += w2 * bf_lo(u2); b2 += w2 * bf_hi(u2);
                a3 += w3 * bf_lo(u3); b3 += w3 * bf_hi(u3);
                a0 += w4 * bf_lo(u4); b0 += w4 * bf_hi(u4);
                a1 += w5 * bf_lo(u5); b1 += w5 * bf_hi(u5);
                a2 += w6 * bf_lo(u6); b2 += w6 * bf_hi(u6);
                a3 += w7 * bf_lo(u7); b3 += w7 * bf_hi(u7);
            }
        }
        float lo = (a0 + a1) + (a2 + a3);     // row r2
        float hi = (b0 + b1) + (b2 + b3);     // row r2+64
        Cg2[r2 * CGS + s] = pack_bf16(hi, lo);
    }
}

__global__ void __launch_bounds__(256, 2)
gemm_y_gather_kernel(const float* __restrict__ Wmat,
                     const float* __restrict__ bias,
                     const int* __restrict__ sl_idx,
                     const float* __restrict__ sl_w,
                     float* __restrict__ outp) {
    extern __shared__ float smem[];
    const uint32_t sbase = smem_u32(smem);
    int tid = threadIdx.x;
    int n0 = blockIdx.x * NBLK;
    float*    Cy  = smem;                               // stride CYP (post-mainloop)
    uint32_t* Cg2 = reinterpret_cast<uint32_t*>(smem + CG2_F);

    // Phase order: wave-1 co-residents are blocks {i, i+148} -> give the
    // second 148 blocks the opposite order so each SM overlaps tensor + L2.
    bool gather_first = ((blockIdx.x / 148) & 1) != 0;

    if (gather_first) {
        do_gather(Cg2, sl_idx, sl_w, n0, tid);
        __syncthreads();
    }

    // ---- GEMM phase ----
    {
        int wid = tid >> 5, lane = tid & 31;
        GemmCtx t;
        t.tid = tid;
        t.mw = wid >> 2; t.nw = wid & 3;
        t.g = lane >> 2; t.tig = lane & 3;
        t.n0 = n0;

        float c[4][4][4];
        #pragma unroll
        for (int mf = 0; mf < 4; mf++)
            #pragma unroll
            for (int nf = 0; nf < 4; nf++)
                #pragma unroll
                for (int i = 0; i < 4; i++) c[mf][nf][i] = 0.f;

        gemm_mainloop(smem, sbase, Wmat, S_, t, c);

        // scatter frags to Cy (pipeline region free after mainloop)
        #pragma unroll
        for (int mf = 0; mf < 4; mf++) {
            int row = t.mw * 64 + mf * 16 + t.g;
            #pragma unroll
            for (int nf = 0; nf < 4; nf++) {
                int cl = t.nw * 32 + nf * 8 + 2 * t.tig;
                Cy[row * CYP + cl]           = c[mf][nf][0];
                Cy[row * CYP + cl + 1]       = c[mf][nf][1];
                Cy[(row + 8) * CYP + cl]     = c[mf][nf][2];
                Cy[(row + 8) * CYP + cl + 1] = c[mf][nf][3];
            }
        }
    }
    __syncthreads();

    if (!gather_first) {
        do_gather(Cg2, sl_idx, sl_w, n0, tid);
        __syncthreads();
    }

    // ---- epilogue: out = Cy + bias + SLM_SCALE * unpack(Cg2) ----
    #pragma unroll
    for (int i = 0; i < 16; i++) {
        int q = tid + i * 256;            // 0..4095
        int row = q >> 5, c4 = (q & 31) * 4;
        int col = n0 + c4;
        if (col < S_) {                   // S % 4 == 0
            float4 bv = *reinterpret_cast<const float4*>(bias + col);
            const float* cy = &Cy[row * CYP + c4];
            const uint32_t* cg = &Cg2[(row & 63) * CGS + c4];
            bool hi = row >= 64;
            float g0 = hi ? bf_hi(cg[0]) : bf_lo(cg[0]);
            float g1 = hi ? bf_hi(cg[1]) : bf_lo(cg[1]);
            float g2 = hi ? bf_hi(cg[2]) : bf_lo(cg[2]);
            float g3 = hi ? bf_hi(cg[3]) : bf_lo(cg[3]);
            float4 o;
            o.x = cy[0] + bv.x + SLM_SCALE * g0;
            o.y = cy[1] + bv.y + SLM_SCALE * g1;
            o.z = cy[2] + bv.z + SLM_SCALE * g2;
            o.w = cy[3] + bv.w + SLM_SCALE * g3;
            *reinterpret_cast<float4*>(&outp[(size_t)row * S_ + col]) = o;
        }
    }
}

// ---------------- launch ----------------------------------------------------
extern "C" void kernel_launch(void* const* d_in, const int* in_sizes, int n_in,
                              void* d_out, int out_size) {
    const float* x     = (const float*)d_in[0];
    const float* gamma = (const float*)d_in[1];
    const float* beta  = (const float*)d_in[2];
    const float* W1    = (const float*)d_in[3];
    const float* b1    = (const float*)d_in[4];
    const float* W2    = (const float*)d_in[5];
    const float* b2    = (const float*)d_in[6];
    const float* Wslm  = (const float*)d_in[7];
    const float* bslm  = (const float*)d_in[8];
    const float* slw   = (const float*)d_in[9];
    const int*   sli   = (const int*)d_in[10];
    float* out = (float*)d_out;

    cudaFuncSetAttribute(gemm_v_kernel,
                         cudaFuncAttributeMaxDynamicSharedMemorySize, GEMMV_SMEM);
    cudaFuncSetAttribute(gemm_y_gather_kernel,
                         cudaFuncAttributeMaxDynamicSharedMemorySize, FUSED_SMEM);

    bn_stats_kernel<<<L_, 256>>>(x, gamma, beta);
    h_kernel<<<dim3(L_, 2), 512>>>(x, W1, b1);
    gemm_v_kernel<<<(V_ + NBLK - 1) / NBLK, 256, GEMMV_SMEM>>>(Wslm, bslm, V_);
    gemm_y_gather_kernel<<<(S_ + NBLK - 1) / NBLK, 256, FUSED_SMEM>>>(
        W2, b2, sli, slw, out);
}